// round 5
// baseline (speedup 1.0000x reference)
#include <cuda_runtime.h>
#include <cuda_fp16.h>
#include <cstdint>

#define D    256
#define N0c  200000
#define N1c  40000
#define N2c  8000
#define E1c  1000000
#define E2c  200000

// ---- scratch (no allocations allowed) ----
__device__ __half g_nodesh[(size_t)N0c * D];   // fp16 node table (102 MB)
__device__ __half g_h1h[(size_t)N1c * D];      // fp16 h1 for layer-2 gather
__device__ float g_mean1[N1c * D];
__device__ float g_h1[N1c * D];
__device__ float g_mean2[N2c * D];
__device__ int g_cnt1[N1c];
__device__ int g_start1[N1c];
__device__ int g_cur1[N1c];
__device__ int g_cnt2[N2c];
__device__ int g_start2[N2c];
__device__ int g_cur2[N2c];
__device__ int g_ss1[E1c];
__device__ int g_ss2[E2c];

// ---- zero ints ----
__global__ void k_zero_i(int* __restrict__ p, int n) {
    int i = blockIdx.x * blockDim.x + threadIdx.x;
    if (i < n) p[i] = 0;
}

// ---- fp32 -> fp16 conversion, 8 floats / thread ----
__global__ void k_cvt(const float4* __restrict__ in, uint4* __restrict__ out, int n8) {
    int i = blockIdx.x * blockDim.x + threadIdx.x;
    int stride = gridDim.x * blockDim.x;
    for (; i < n8; i += stride) {
        float4 a = __ldg(in + 2 * i);
        float4 b = __ldg(in + 2 * i + 1);
        __half2 h[4];
        h[0] = __floats2half2_rn(a.x, a.y);
        h[1] = __floats2half2_rn(a.z, a.w);
        h[2] = __floats2half2_rn(b.x, b.y);
        h[3] = __floats2half2_rn(b.z, b.w);
        out[i] = *reinterpret_cast<uint4*>(h);
    }
}

// ---- histogram of dst ----
__global__ void k_hist(const int* __restrict__ dst, int* __restrict__ cnt, int ne) {
    int i = blockIdx.x * blockDim.x + threadIdx.x;
    int stride = gridDim.x * blockDim.x;
    for (; i < ne; i += stride) atomicAdd(&cnt[dst[i]], 1);
}

// ---- thread-coarsened single-block exclusive scan (1 block, 1024 threads) ----
__global__ __launch_bounds__(1024) void k_scan_fast(
    const int* __restrict__ cnt, int* __restrict__ start,
    int* __restrict__ cursor, int n)
{
    __shared__ int wsum[32];
    const int tid = threadIdx.x;
    const int lane = tid & 31;
    const int wid = tid >> 5;
    const int C = (n + 1023) >> 10;        // chunk per thread
    const int lo = tid * C;
    const int hi = (lo + C < n) ? lo + C : n;

    // local sum
    int s = 0;
    for (int i = lo; i < hi; i++) s += __ldg(cnt + i);

    // block inclusive scan of per-thread sums
    int x = s;
#pragma unroll
    for (int o = 1; o < 32; o <<= 1) {
        int y = __shfl_up_sync(~0u, x, o);
        if (lane >= o) x += y;
    }
    if (lane == 31) wsum[wid] = x;
    __syncthreads();
    if (tid < 32) {
        int w = wsum[tid];
#pragma unroll
        for (int o = 1; o < 32; o <<= 1) {
            int y = __shfl_up_sync(~0u, w, o);
            if (tid >= o) w += y;
        }
        wsum[tid] = w;
    }
    __syncthreads();
    const int wpref = (wid > 0) ? wsum[wid - 1] : 0;
    int run = x - s + wpref;               // exclusive prefix of this thread's chunk

    // write per-element exclusive prefixes
    for (int i = lo; i < hi; i++) {
        const int v = __ldg(cnt + i);
        start[i] = run;
        cursor[i] = run;
        run += v;
    }
}

// ---- bucket-scatter src ids into dst-sorted order ----
__global__ void k_sidx(const int* __restrict__ src, const int* __restrict__ dst,
                       int* __restrict__ cursor, int* __restrict__ ss, int ne) {
    int i = blockIdx.x * blockDim.x + threadIdx.x;
    int stride = gridDim.x * blockDim.x;
    for (; i < ne; i += stride) {
        int d = dst[i];
        int p = atomicAdd(&cursor[d], 1);
        ss[p] = src[i];
    }
}

// ---- gather-aggregate (fp16 table): one warp per dst node, 8-deep MLP batches ----
__global__ __launch_bounds__(256) void k_gather_h(
    const __half* __restrict__ x, const int* __restrict__ ss,
    const int* __restrict__ start, const int* __restrict__ cnt,
    float* __restrict__ mean, int n)
{
    int w = (blockIdx.x * blockDim.x + threadIdx.x) >> 5;
    if (w >= n) return;
    const int lane = threadIdx.x & 31;
    const int beg = __ldg(start + w);
    const int c = __ldg(cnt + w);
    const int end = beg + c;

    float acc[8];
#pragma unroll
    for (int j = 0; j < 8; j++) acc[j] = 0.f;

    int i = beg;
    for (; i + 8 <= end; i += 8) {
        int s[8];
#pragma unroll
        for (int j = 0; j < 8; j++) s[j] = __ldg(ss + i + j);
        uint4 v[8];
#pragma unroll
        for (int j = 0; j < 8; j++)
            v[j] = __ldg(reinterpret_cast<const uint4*>(x + (size_t)s[j] * D) + lane);
#pragma unroll
        for (int j = 0; j < 8; j++) {
            const __half2* p = reinterpret_cast<const __half2*>(&v[j]);
#pragma unroll
            for (int q = 0; q < 4; q++) {
                float2 f = __half22float2(p[q]);
                acc[2 * q]     += f.x;
                acc[2 * q + 1] += f.y;
            }
        }
    }
    // tail (<8) with 4-then-1
    for (; i + 4 <= end; i += 4) {
        int s[4];
#pragma unroll
        for (int j = 0; j < 4; j++) s[j] = __ldg(ss + i + j);
        uint4 v[4];
#pragma unroll
        for (int j = 0; j < 4; j++)
            v[j] = __ldg(reinterpret_cast<const uint4*>(x + (size_t)s[j] * D) + lane);
#pragma unroll
        for (int j = 0; j < 4; j++) {
            const __half2* p = reinterpret_cast<const __half2*>(&v[j]);
#pragma unroll
            for (int q = 0; q < 4; q++) {
                float2 f = __half22float2(p[q]);
                acc[2 * q]     += f.x;
                acc[2 * q + 1] += f.y;
            }
        }
    }
    for (; i < end; i++) {
        const int s0 = __ldg(ss + i);
        uint4 v0 = __ldg(reinterpret_cast<const uint4*>(x + (size_t)s0 * D) + lane);
        const __half2* p = reinterpret_cast<const __half2*>(&v0);
#pragma unroll
        for (int q = 0; q < 4; q++) {
            float2 f = __half22float2(p[q]);
            acc[2 * q]     += f.x;
            acc[2 * q + 1] += f.y;
        }
    }

    const float inv = 1.0f / fmaxf((float)c, 1.0f);
    float4 w0 = make_float4(acc[0] * inv, acc[1] * inv, acc[2] * inv, acc[3] * inv);
    float4 w1 = make_float4(acc[4] * inv, acc[5] * inv, acc[6] * inv, acc[7] * inv);
    float4* mr = reinterpret_cast<float4*>(mean + (size_t)w * D);
    mr[2 * lane]     = w0;
    mr[2 * lane + 1] = w1;
}

// ---- tf32 helpers ----
__device__ __forceinline__ uint32_t f2tf(float f) {
    uint32_t u;
    asm("cvt.rna.tf32.f32 %0, %1;" : "=r"(u) : "f"(f));
    return u;
}

__device__ __forceinline__ void mma_tf32(float c[4], const uint32_t a[4], const uint32_t b[2]) {
    asm volatile(
        "mma.sync.aligned.m16n8k8.row.col.f32.tf32.tf32.f32 "
        "{%0,%1,%2,%3}, {%4,%5,%6,%7}, {%8,%9}, {%0,%1,%2,%3};"
        : "+f"(c[0]), "+f"(c[1]), "+f"(c[2]), "+f"(c[3])
        : "r"(a[0]), "r"(a[1]), "r"(a[2]), "r"(a[3]), "r"(b[0]), "r"(b[1]));
}

// ---- fused SAGE layer GEMM (tf32 tensor cores), optional fp16 secondary output ----
__global__ __launch_bounds__(256) void k_sage_mma(
    const float* __restrict__ mean,
    const float* __restrict__ xt, const float* __restrict__ Wl,
    const float* __restrict__ Wr, const float* __restrict__ bias,
    float* __restrict__ out, __half* __restrict__ out_h, int M)
{
    __shared__ uint32_t As[128][20];
    __shared__ uint32_t Bs[128][20];

    const int m0 = blockIdx.x * 128;
    const int n0 = blockIdx.y * 128;
    const int t  = threadIdx.x;

    const int lrow = t >> 1;
    const int half = t & 1;
    const int gm   = m0 + lrow;
    const bool mval = gm < M;
    const float* mrow = mean + (size_t)gm * D;
    const float* xrow = xt  + (size_t)gm * D;
    const int gj = n0 + lrow;

    const int warp = t >> 5;
    const int lane = t & 31;
    const int gid  = lane >> 2;
    const int tig  = lane & 3;
    const int wm0  = (warp & 1) * 64;
    const int wn0  = (warp >> 1) * 32;

    float acc[4][4][4];
#pragma unroll
    for (int mf = 0; mf < 4; mf++)
#pragma unroll
        for (int nf = 0; nf < 4; nf++)
#pragma unroll
            for (int r = 0; r < 4; r++) acc[mf][nf][r] = 0.f;

    for (int kt = 0; kt < 32; kt++) {
        const int k0 = kt * 16;
        const bool in_agg = (k0 < 256);
        const int kk0 = in_agg ? k0 : (k0 - 256);

        float4 a0 = make_float4(0.f, 0.f, 0.f, 0.f), a1 = a0;
        if (mval) {
            const float* sp = (in_agg ? mrow : xrow) + kk0 + half * 8;
            a0 = *reinterpret_cast<const float4*>(sp);
            a1 = *reinterpret_cast<const float4*>(sp + 4);
        }
        const float* W  = in_agg ? Wl : Wr;
        const float* bp = W + (size_t)gj * D + kk0 + half * 8;
        float4 b0v = *reinterpret_cast<const float4*>(bp);
        float4 b1v = *reinterpret_cast<const float4*>(bp + 4);

        __syncthreads();
        {
            const int kb = half * 8;
            As[lrow][kb + 0] = f2tf(a0.x); As[lrow][kb + 1] = f2tf(a0.y);
            As[lrow][kb + 2] = f2tf(a0.z); As[lrow][kb + 3] = f2tf(a0.w);
            As[lrow][kb + 4] = f2tf(a1.x); As[lrow][kb + 5] = f2tf(a1.y);
            As[lrow][kb + 6] = f2tf(a1.z); As[lrow][kb + 7] = f2tf(a1.w);
            Bs[lrow][kb + 0] = f2tf(b0v.x); Bs[lrow][kb + 1] = f2tf(b0v.y);
            Bs[lrow][kb + 2] = f2tf(b0v.z); Bs[lrow][kb + 3] = f2tf(b0v.w);
            Bs[lrow][kb + 4] = f2tf(b1v.x); Bs[lrow][kb + 5] = f2tf(b1v.y);
            Bs[lrow][kb + 6] = f2tf(b1v.z); Bs[lrow][kb + 7] = f2tf(b1v.w);
        }
        __syncthreads();

#pragma unroll
        for (int k8 = 0; k8 < 2; k8++) {
            const int kb2 = k8 * 8;
            uint32_t af[4][4], bf[4][2];
#pragma unroll
            for (int mf = 0; mf < 4; mf++) {
                const int r = wm0 + mf * 16 + gid;
                af[mf][0] = As[r][kb2 + tig];
                af[mf][1] = As[r + 8][kb2 + tig];
                af[mf][2] = As[r][kb2 + tig + 4];
                af[mf][3] = As[r + 8][kb2 + tig + 4];
            }
#pragma unroll
            for (int nf = 0; nf < 4; nf++) {
                const int c = wn0 + nf * 8 + gid;
                bf[nf][0] = Bs[c][kb2 + tig];
                bf[nf][1] = Bs[c][kb2 + tig + 4];
            }
#pragma unroll
            for (int mf = 0; mf < 4; mf++)
#pragma unroll
                for (int nf = 0; nf < 4; nf++)
                    mma_tf32(acc[mf][nf], af[mf], bf[nf]);
        }
    }

#pragma unroll
    for (int nf = 0; nf < 4; nf++) {
        const int cb = n0 + wn0 + nf * 8 + tig * 2;
        const float bx = __ldg(bias + cb);
        const float by = __ldg(bias + cb + 1);
#pragma unroll
        for (int mf = 0; mf < 4; mf++) {
            const int r0 = m0 + wm0 + mf * 16 + gid;
            if (r0 < M) {
                float2 v;
                v.x = tanhf(acc[mf][nf][0] + bx);
                v.y = tanhf(acc[mf][nf][1] + by);
                *reinterpret_cast<float2*>(out + (size_t)r0 * D + cb) = v;
                if (out_h)
                    *reinterpret_cast<__half2*>(out_h + (size_t)r0 * D + cb) =
                        __floats2half2_rn(v.x, v.y);
            }
            const int r1 = r0 + 8;
            if (r1 < M) {
                float2 v;
                v.x = tanhf(acc[mf][nf][2] + bx);
                v.y = tanhf(acc[mf][nf][3] + by);
                *reinterpret_cast<float2*>(out + (size_t)r1 * D + cb) = v;
                if (out_h)
                    *reinterpret_cast<__half2*>(out_h + (size_t)r1 * D + cb) =
                        __floats2half2_rn(v.x, v.y);
            }
        }
    }
}

extern "C" void kernel_launch(void* const* d_in, const int* in_sizes, int n_in,
                              void* d_out, int out_size) {
    const float* nodes = (const float*)d_in[0];
    const float* W_l1  = (const float*)d_in[1];
    const float* b1    = (const float*)d_in[2];
    const float* W_r1  = (const float*)d_in[3];
    const float* W_l2  = (const float*)d_in[4];
    const float* b2    = (const float*)d_in[5];
    const float* W_r2  = (const float*)d_in[6];
    const int*   src1  = (const int*)d_in[7];
    const int*   dst1  = (const int*)d_in[8];
    const int*   src2  = (const int*)d_in[9];
    const int*   dst2  = (const int*)d_in[10];
    float* out = (float*)d_out;

    float *mean1, *h1, *mean2;
    __half *nodesh, *h1h;
    int *cnt1, *start1, *cur1, *cnt2, *start2, *cur2, *ss1, *ss2;
    cudaGetSymbolAddress((void**)&nodesh, g_nodesh);
    cudaGetSymbolAddress((void**)&h1h,    g_h1h);
    cudaGetSymbolAddress((void**)&mean1,  g_mean1);
    cudaGetSymbolAddress((void**)&h1,     g_h1);
    cudaGetSymbolAddress((void**)&mean2,  g_mean2);
    cudaGetSymbolAddress((void**)&cnt1,   g_cnt1);
    cudaGetSymbolAddress((void**)&start1, g_start1);
    cudaGetSymbolAddress((void**)&cur1,   g_cur1);
    cudaGetSymbolAddress((void**)&cnt2,   g_cnt2);
    cudaGetSymbolAddress((void**)&start2, g_start2);
    cudaGetSymbolAddress((void**)&cur2,   g_cur2);
    cudaGetSymbolAddress((void**)&ss1,    g_ss1);
    cudaGetSymbolAddress((void**)&ss2,    g_ss2);

    // fp16 node table
    {
        int n8 = (int)(((size_t)N0c * D) / 8);
        k_cvt<<<2368, 256>>>((const float4*)nodes, (uint4*)nodesh, n8);
    }

    // ---- layer 1 ----
    k_zero_i<<<(N1c + 255) / 256, 256>>>(cnt1, N1c);
    k_hist<<<592, 256>>>(dst1, cnt1, E1c);
    k_scan_fast<<<1, 1024>>>(cnt1, start1, cur1, N1c);
    k_sidx<<<592, 256>>>(src1, dst1, cur1, ss1, E1c);
    k_gather_h<<<(N1c * 32 + 255) / 256, 256>>>(nodesh, ss1, start1, cnt1, mean1, N1c);
    {
        dim3 grid((N1c + 127) / 128, 2);
        k_sage_mma<<<grid, 256>>>(mean1, nodes, W_l1, W_r1, b1, h1, h1h, N1c);
    }

    // ---- layer 2 ----
    k_zero_i<<<(N2c + 255) / 256, 256>>>(cnt2, N2c);
    k_hist<<<592, 256>>>(dst2, cnt2, E2c);
    k_scan_fast<<<1, 1024>>>(cnt2, start2, cur2, N2c);
    k_sidx<<<592, 256>>>(src2, dst2, cur2, ss2, E2c);
    k_gather_h<<<(N2c * 32 + 255) / 256, 256>>>(h1h, ss2, start2, cnt2, mean2, N2c);
    {
        dim3 grid((N2c + 127) / 128, 2);
        k_sage_mma<<<grid, 256>>>(mean2, h1, W_l2, W_r2, b2, out, ((__half*)0), N2c);
    }
}

// round 6
// speedup vs baseline: 1.4218x; 1.4218x over previous
#include <cuda_runtime.h>
#include <cuda_fp16.h>
#include <cstdint>

#define D    256
#define N0c  200000
#define N1c  40000
#define N2c  8000
#define E1c  1000000
#define E2c  200000

// ---- scratch (no allocations allowed) ----
__device__ __half g_nodesh[(size_t)N0c * D];   // fp16 node table (102 MB)
__device__ __half g_h1h[(size_t)N1c * D];      // fp16 h1
__device__ __half g_mean1h[(size_t)N1c * D];
__device__ __half g_mean2h[(size_t)N2c * D];
__device__ int g_cnt1[N1c];
__device__ int g_start1[N1c];
__device__ int g_cur1[N1c];
__device__ int g_cnt2[N2c];
__device__ int g_start2[N2c];
__device__ int g_cur2[N2c];
__device__ int g_ss1[E1c];
__device__ int g_ss2[E2c];

// ---- zero both count arrays ----
__global__ void k_init(int* __restrict__ c1, int* __restrict__ c2) {
    int i = blockIdx.x * blockDim.x + threadIdx.x;
    if (i < N1c) c1[i] = 0;
    if (i < N2c) c2[i] = 0;
}

// ---- fused: fp32->fp16 table conversion + both dst histograms ----
__global__ void k_cvt_hist(const float4* __restrict__ in, uint4* __restrict__ out, int n8,
                           const int* __restrict__ dst1, int* __restrict__ cnt1, int e1,
                           const int* __restrict__ dst2, int* __restrict__ cnt2, int e2) {
    const int i0 = blockIdx.x * blockDim.x + threadIdx.x;
    const int stride = gridDim.x * blockDim.x;
    for (int i = i0; i < n8; i += stride) {
        float4 a = __ldg(in + 2 * i);
        float4 b = __ldg(in + 2 * i + 1);
        __half2 h[4];
        h[0] = __floats2half2_rn(a.x, a.y);
        h[1] = __floats2half2_rn(a.z, a.w);
        h[2] = __floats2half2_rn(b.x, b.y);
        h[3] = __floats2half2_rn(b.z, b.w);
        out[i] = *reinterpret_cast<uint4*>(h);
    }
    for (int i = i0; i < e1; i += stride) atomicAdd(&cnt1[__ldg(dst1 + i)], 1);
    for (int i = i0; i < e2; i += stride) atomicAdd(&cnt2[__ldg(dst2 + i)], 1);
}

// ---- tiled coalesced single-block exclusive scan (int4 per thread per tile) ----
__global__ __launch_bounds__(1024) void k_scan_t(
    const int4* __restrict__ cnt4, int4* __restrict__ start4,
    int4* __restrict__ cursor4, int n4)
{
    __shared__ int wsum[32];
    __shared__ int carry;
    const int tid = threadIdx.x;
    const int lane = tid & 31;
    const int wid = tid >> 5;
    if (tid == 0) carry = 0;
    __syncthreads();
    for (int base = 0; base < n4; base += 1024) {
        const int i = base + tid;
        int4 v = (i < n4) ? __ldg(cnt4 + i) : make_int4(0, 0, 0, 0);
        const int s = v.x + v.y + v.z + v.w;
        int x = s;
#pragma unroll
        for (int o = 1; o < 32; o <<= 1) {
            int y = __shfl_up_sync(~0u, x, o);
            if (lane >= o) x += y;
        }
        if (lane == 31) wsum[wid] = x;
        __syncthreads();
        if (tid < 32) {
            int w = wsum[tid];
#pragma unroll
            for (int o = 1; o < 32; o <<= 1) {
                int y = __shfl_up_sync(~0u, w, o);
                if (tid >= o) w += y;
            }
            wsum[tid] = w;
        }
        __syncthreads();
        const int wpref = (wid > 0) ? wsum[wid - 1] : 0;
        const int e = x - s + wpref + carry;
        if (i < n4) {
            int4 st;
            st.x = e; st.y = e + v.x; st.z = st.y + v.y; st.w = st.z + v.z;
            start4[i] = st;
            cursor4[i] = st;
        }
        __syncthreads();
        if (tid == 0) carry += wsum[31];
        __syncthreads();
    }
}

// ---- bucket-scatter src ids into dst-sorted order ----
__global__ void k_sidx(const int* __restrict__ src, const int* __restrict__ dst,
                       int* __restrict__ cursor, int* __restrict__ ss, int ne) {
    int i = blockIdx.x * blockDim.x + threadIdx.x;
    int stride = gridDim.x * blockDim.x;
    for (; i < ne; i += stride) {
        int d = dst[i];
        int p = atomicAdd(&cursor[d], 1);
        ss[p] = src[i];
    }
}

// ---- gather-aggregate (fp16 table): one warp per dst node, MLP-batched, fp16 MEAN out ----
__global__ __launch_bounds__(256) void k_gather_h(
    const __half* __restrict__ x, const int* __restrict__ ss,
    const int* __restrict__ start, const int* __restrict__ cnt,
    __half* __restrict__ mean, int n)
{
    int w = (blockIdx.x * blockDim.x + threadIdx.x) >> 5;
    if (w >= n) return;
    const int lane = threadIdx.x & 31;
    const int beg = __ldg(start + w);
    const int c = __ldg(cnt + w);
    const int end = beg + c;

    float acc[8];
#pragma unroll
    for (int j = 0; j < 8; j++) acc[j] = 0.f;

    int i = beg;
    for (; i + 8 <= end; i += 8) {
        int s[8];
#pragma unroll
        for (int j = 0; j < 8; j++) s[j] = __ldg(ss + i + j);
        uint4 v[8];
#pragma unroll
        for (int j = 0; j < 8; j++)
            v[j] = __ldg(reinterpret_cast<const uint4*>(x + (size_t)s[j] * D) + lane);
#pragma unroll
        for (int j = 0; j < 8; j++) {
            const __half2* p = reinterpret_cast<const __half2*>(&v[j]);
#pragma unroll
            for (int q = 0; q < 4; q++) {
                float2 f = __half22float2(p[q]);
                acc[2 * q]     += f.x;
                acc[2 * q + 1] += f.y;
            }
        }
    }
    for (; i + 4 <= end; i += 4) {
        int s[4];
#pragma unroll
        for (int j = 0; j < 4; j++) s[j] = __ldg(ss + i + j);
        uint4 v[4];
#pragma unroll
        for (int j = 0; j < 4; j++)
            v[j] = __ldg(reinterpret_cast<const uint4*>(x + (size_t)s[j] * D) + lane);
#pragma unroll
        for (int j = 0; j < 4; j++) {
            const __half2* p = reinterpret_cast<const __half2*>(&v[j]);
#pragma unroll
            for (int q = 0; q < 4; q++) {
                float2 f = __half22float2(p[q]);
                acc[2 * q]     += f.x;
                acc[2 * q + 1] += f.y;
            }
        }
    }
    for (; i < end; i++) {
        const int s0 = __ldg(ss + i);
        uint4 v0 = __ldg(reinterpret_cast<const uint4*>(x + (size_t)s0 * D) + lane);
        const __half2* p = reinterpret_cast<const __half2*>(&v0);
#pragma unroll
        for (int q = 0; q < 4; q++) {
            float2 f = __half22float2(p[q]);
            acc[2 * q]     += f.x;
            acc[2 * q + 1] += f.y;
        }
    }

    const float inv = 1.0f / fmaxf((float)c, 1.0f);
    __half2 o[4];
#pragma unroll
    for (int q = 0; q < 4; q++)
        o[q] = __floats2half2_rn(acc[2 * q] * inv, acc[2 * q + 1] * inv);
    reinterpret_cast<uint4*>(mean + (size_t)w * D)[lane] = *reinterpret_cast<uint4*>(o);
}

// ---- fp16 mma helper (m16n8k16, fp32 accumulate) ----
__device__ __forceinline__ void mma_f16(float c[4], const uint32_t a[4], const uint32_t b[2]) {
    asm volatile(
        "mma.sync.aligned.m16n8k16.row.col.f32.f16.f16.f32 "
        "{%0,%1,%2,%3}, {%4,%5,%6,%7}, {%8,%9}, {%0,%1,%2,%3};"
        : "+f"(c[0]), "+f"(c[1]), "+f"(c[2]), "+f"(c[3])
        : "r"(a[0]), "r"(a[1]), "r"(a[2]), "r"(a[3]), "r"(b[0]), "r"(b[1]));
}

// ---- fused SAGE layer GEMM (fp16 tensor cores, fp32 accum):
//   out[m, j] = tanh( sum_k mean[m,k]*Wl[j,k] + sum_k xt[m,k]*Wr[j,k] + b[j] )
// A = [mean | xt] (M x 512, fp16), B^T = [Wl | Wr] (256 x 512, fp32 -> fp16).
// smem: half2 pairs, [row][pair] with stride 12 (conflict-free for 8g x 4t pattern).
__global__ __launch_bounds__(256) void k_sage_mma_h(
    const __half* __restrict__ meanh, const __half* __restrict__ xth,
    const float* __restrict__ Wl, const float* __restrict__ Wr,
    const float* __restrict__ bias,
    float* __restrict__ out, __half* __restrict__ out_h, int M)
{
    __shared__ uint32_t As[128][12];
    __shared__ uint32_t Bs[128][12];

    const int m0 = blockIdx.x * 128;
    const int n0 = blockIdx.y * 128;
    const int t  = threadIdx.x;

    const int lrow = t >> 1;
    const int half = t & 1;
    const int gm   = m0 + lrow;
    const bool mval = gm < M;
    const __half* mrow = meanh + (size_t)gm * D;
    const __half* xrow = xth  + (size_t)gm * D;
    const int gj = n0 + lrow;

    const int warp = t >> 5;
    const int lane = t & 31;
    const int gid  = lane >> 2;
    const int tig  = lane & 3;
    const int wm0  = (warp & 1) * 64;
    const int wn0  = (warp >> 1) * 32;

    float acc[4][4][4];
#pragma unroll
    for (int mf = 0; mf < 4; mf++)
#pragma unroll
        for (int nf = 0; nf < 4; nf++)
#pragma unroll
            for (int r = 0; r < 4; r++) acc[mf][nf][r] = 0.f;

    for (int kt = 0; kt < 32; kt++) {
        const int k0 = kt * 16;
        const bool in_agg = (k0 < 256);
        const int kk0 = in_agg ? k0 : (k0 - 256);

        // A: 8 halves (16B) per thread, already fp16
        uint4 av = make_uint4(0, 0, 0, 0);
        if (mval) {
            const __half* sp = (in_agg ? mrow : xrow) + kk0 + half * 8;
            av = *reinterpret_cast<const uint4*>(sp);
        }
        // B: 8 floats per thread -> 4 half2
        const float* W  = in_agg ? Wl : Wr;
        const float* bp = W + (size_t)gj * D + kk0 + half * 8;
        float4 b0v = *reinterpret_cast<const float4*>(bp);
        float4 b1v = *reinterpret_cast<const float4*>(bp + 4);
        __half2 bh[4];
        bh[0] = __floats2half2_rn(b0v.x, b0v.y);
        bh[1] = __floats2half2_rn(b0v.z, b0v.w);
        bh[2] = __floats2half2_rn(b1v.x, b1v.y);
        bh[3] = __floats2half2_rn(b1v.z, b1v.w);

        __syncthreads();
        *reinterpret_cast<uint4*>(&As[lrow][half * 4]) = av;
        *reinterpret_cast<uint4*>(&Bs[lrow][half * 4]) = *reinterpret_cast<uint4*>(bh);
        __syncthreads();

        uint32_t af[4][4], bf[4][2];
#pragma unroll
        for (int mf = 0; mf < 4; mf++) {
            const int r = wm0 + mf * 16 + gid;
            af[mf][0] = As[r][tig];
            af[mf][1] = As[r + 8][tig];
            af[mf][2] = As[r][tig + 4];
            af[mf][3] = As[r + 8][tig + 4];
        }
#pragma unroll
        for (int nf = 0; nf < 4; nf++) {
            const int c = wn0 + nf * 8 + gid;
            bf[nf][0] = Bs[c][tig];
            bf[nf][1] = Bs[c][tig + 4];
        }
#pragma unroll
        for (int mf = 0; mf < 4; mf++)
#pragma unroll
            for (int nf = 0; nf < 4; nf++)
                mma_f16(acc[mf][nf], af[mf], bf[nf]);
    }

#pragma unroll
    for (int nf = 0; nf < 4; nf++) {
        const int cb = n0 + wn0 + nf * 8 + tig * 2;
        const float bx = __ldg(bias + cb);
        const float by = __ldg(bias + cb + 1);
#pragma unroll
        for (int mf = 0; mf < 4; mf++) {
            const int r0 = m0 + wm0 + mf * 16 + gid;
            if (r0 < M) {
                float vx = tanhf(acc[mf][nf][0] + bx);
                float vy = tanhf(acc[mf][nf][1] + by);
                if (out)
                    *reinterpret_cast<float2*>(out + (size_t)r0 * D + cb) = make_float2(vx, vy);
                if (out_h)
                    *reinterpret_cast<__half2*>(out_h + (size_t)r0 * D + cb) =
                        __floats2half2_rn(vx, vy);
            }
            const int r1 = r0 + 8;
            if (r1 < M) {
                float vx = tanhf(acc[mf][nf][2] + bx);
                float vy = tanhf(acc[mf][nf][3] + by);
                if (out)
                    *reinterpret_cast<float2*>(out + (size_t)r1 * D + cb) = make_float2(vx, vy);
                if (out_h)
                    *reinterpret_cast<__half2*>(out_h + (size_t)r1 * D + cb) =
                        __floats2half2_rn(vx, vy);
            }
        }
    }
}

extern "C" void kernel_launch(void* const* d_in, const int* in_sizes, int n_in,
                              void* d_out, int out_size) {
    const float* nodes = (const float*)d_in[0];
    const float* W_l1  = (const float*)d_in[1];
    const float* b1    = (const float*)d_in[2];
    const float* W_r1  = (const float*)d_in[3];
    const float* W_l2  = (const float*)d_in[4];
    const float* b2    = (const float*)d_in[5];
    const float* W_r2  = (const float*)d_in[6];
    const int*   src1  = (const int*)d_in[7];
    const int*   dst1  = (const int*)d_in[8];
    const int*   src2  = (const int*)d_in[9];
    const int*   dst2  = (const int*)d_in[10];
    float* out = (float*)d_out;

    __half *nodesh, *h1h, *mean1h, *mean2h;
    int *cnt1, *start1, *cur1, *cnt2, *start2, *cur2, *ss1, *ss2;
    cudaGetSymbolAddress((void**)&nodesh, g_nodesh);
    cudaGetSymbolAddress((void**)&h1h,    g_h1h);
    cudaGetSymbolAddress((void**)&mean1h, g_mean1h);
    cudaGetSymbolAddress((void**)&mean2h, g_mean2h);
    cudaGetSymbolAddress((void**)&cnt1,   g_cnt1);
    cudaGetSymbolAddress((void**)&start1, g_start1);
    cudaGetSymbolAddress((void**)&cur1,   g_cur1);
    cudaGetSymbolAddress((void**)&cnt2,   g_cnt2);
    cudaGetSymbolAddress((void**)&start2, g_start2);
    cudaGetSymbolAddress((void**)&cur2,   g_cur2);
    cudaGetSymbolAddress((void**)&ss1,    g_ss1);
    cudaGetSymbolAddress((void**)&ss2,    g_ss2);

    // init counters
    k_init<<<(N1c + 255) / 256, 256>>>(cnt1, cnt2);
    // fp16 table + both histograms
    {
        int n8 = (int)(((size_t)N0c * D) / 8);
        k_cvt_hist<<<2368, 256>>>((const float4*)nodes, (uint4*)nodesh, n8,
                                  dst1, cnt1, E1c, dst2, cnt2, E2c);
    }

    // ---- layer 1 ----
    k_scan_t<<<1, 1024>>>((const int4*)cnt1, (int4*)start1, (int4*)cur1, N1c / 4);
    k_sidx<<<592, 256>>>(src1, dst1, cur1, ss1, E1c);
    k_gather_h<<<(N1c * 32 + 255) / 256, 256>>>(nodesh, ss1, start1, cnt1, mean1h, N1c);
    {
        dim3 grid((N1c + 127) / 128, 2);
        k_sage_mma_h<<<grid, 256>>>(mean1h, nodesh, W_l1, W_r1, b1,
                                    ((float*)0), h1h, N1c);
    }

    // ---- layer 2 ----
    k_scan_t<<<1, 1024>>>((const int4*)cnt2, (int4*)start2, (int4*)cur2, N2c / 4);
    k_sidx<<<592, 256>>>(src2, dst2, cur2, ss2, E2c);
    k_gather_h<<<(N2c * 32 + 255) / 256, 256>>>(h1h, ss2, start2, cnt2, mean2h, N2c);
    {
        dim3 grid((N2c + 127) / 128, 2);
        k_sage_mma_h<<<grid, 256>>>(mean2h, h1h, W_l2, W_r2, b2,
                                    out, ((__half*)0), N2c);
    }
}

// round 7
// speedup vs baseline: 1.4591x; 1.0262x over previous
#include <cuda_runtime.h>
#include <cuda_fp16.h>
#include <cstdint>

#define D    256
#define N0c  200000
#define N1c  40000
#define N2c  8000
#define E1c  1000000
#define E2c  200000

// ---- scratch (no allocations allowed) ----
__device__ __half g_nodesh[(size_t)N0c * D];   // fp16 node table (102 MB)
__device__ __half g_h1h[(size_t)N1c * D];      // fp16 h1
__device__ __half g_mean1h[(size_t)N1c * D];
__device__ __half g_mean2h[(size_t)N2c * D];
__device__ int g_cnt1[N1c];
__device__ int g_start1[N1c];
__device__ int g_cur1[N1c];
__device__ int g_cnt2[N2c];
__device__ int g_start2[N2c];
__device__ int g_cur2[N2c];
__device__ int g_ss1[E1c];
__device__ int g_ss2[E2c];

// ---- zero both count arrays ----
__global__ void k_init(int* __restrict__ c1, int* __restrict__ c2) {
    int i = blockIdx.x * blockDim.x + threadIdx.x;
    if (i < N1c) c1[i] = 0;
    if (i < N2c) c2[i] = 0;
}

// ---- fused: fp32->fp16 table conversion + both dst histograms ----
__global__ void k_cvt_hist(const float4* __restrict__ in, uint4* __restrict__ out, int n8,
                           const int* __restrict__ dst1, int* __restrict__ cnt1, int e1,
                           const int* __restrict__ dst2, int* __restrict__ cnt2, int e2) {
    const int i0 = blockIdx.x * blockDim.x + threadIdx.x;
    const int stride = gridDim.x * blockDim.x;
    for (int i = i0; i < n8; i += stride) {
        float4 a = __ldg(in + 2 * i);
        float4 b = __ldg(in + 2 * i + 1);
        __half2 h[4];
        h[0] = __floats2half2_rn(a.x, a.y);
        h[1] = __floats2half2_rn(a.z, a.w);
        h[2] = __floats2half2_rn(b.x, b.y);
        h[3] = __floats2half2_rn(b.z, b.w);
        out[i] = *reinterpret_cast<uint4*>(h);
    }
    for (int i = i0; i < e1; i += stride) atomicAdd(&cnt1[__ldg(dst1 + i)], 1);
    for (int i = i0; i < e2; i += stride) atomicAdd(&cnt2[__ldg(dst2 + i)], 1);
}

// ---- tiled coalesced single-block exclusive scan (int4 per thread per tile) ----
__global__ __launch_bounds__(1024) void k_scan_t(
    const int4* __restrict__ cnt4, int4* __restrict__ start4,
    int4* __restrict__ cursor4, int n4)
{
    __shared__ int wsum[32];
    __shared__ int carry;
    const int tid = threadIdx.x;
    const int lane = tid & 31;
    const int wid = tid >> 5;
    if (tid == 0) carry = 0;
    __syncthreads();
    for (int base = 0; base < n4; base += 1024) {
        const int i = base + tid;
        int4 v = (i < n4) ? __ldg(cnt4 + i) : make_int4(0, 0, 0, 0);
        const int s = v.x + v.y + v.z + v.w;
        int x = s;
#pragma unroll
        for (int o = 1; o < 32; o <<= 1) {
            int y = __shfl_up_sync(~0u, x, o);
            if (lane >= o) x += y;
        }
        if (lane == 31) wsum[wid] = x;
        __syncthreads();
        if (tid < 32) {
            int w = wsum[tid];
#pragma unroll
            for (int o = 1; o < 32; o <<= 1) {
                int y = __shfl_up_sync(~0u, w, o);
                if (tid >= o) w += y;
            }
            wsum[tid] = w;
        }
        __syncthreads();
        const int wpref = (wid > 0) ? wsum[wid - 1] : 0;
        const int e = x - s + wpref + carry;
        if (i < n4) {
            int4 st;
            st.x = e; st.y = e + v.x; st.z = st.y + v.y; st.w = st.z + v.z;
            start4[i] = st;
            cursor4[i] = st;
        }
        __syncthreads();
        if (tid == 0) carry += wsum[31];
        __syncthreads();
    }
}

// ---- bucket-scatter: ONE EDGE PER THREAD (max chip-level MLP, no serial chains) ----
__global__ void k_sidx(const int* __restrict__ src, const int* __restrict__ dst,
                       int* __restrict__ cursor, int* __restrict__ ss, int ne) {
    int i = blockIdx.x * blockDim.x + threadIdx.x;
    if (i < ne) {
        int d = __ldg(dst + i);
        int p = atomicAdd(&cursor[d], 1);
        ss[p] = __ldg(src + i);
    }
}

// ---- gather-aggregate (fp16 table): one warp per dst node, MLP-batched, fp16 MEAN out ----
__global__ __launch_bounds__(256) void k_gather_h(
    const __half* __restrict__ x, const int* __restrict__ ss,
    const int* __restrict__ start, const int* __restrict__ cnt,
    __half* __restrict__ mean, int n)
{
    int w = (blockIdx.x * blockDim.x + threadIdx.x) >> 5;
    if (w >= n) return;
    const int lane = threadIdx.x & 31;
    const int beg = __ldg(start + w);
    const int c = __ldg(cnt + w);
    const int end = beg + c;

    float acc[8];
#pragma unroll
    for (int j = 0; j < 8; j++) acc[j] = 0.f;

    int i = beg;
    for (; i + 8 <= end; i += 8) {
        int s[8];
#pragma unroll
        for (int j = 0; j < 8; j++) s[j] = __ldg(ss + i + j);
        uint4 v[8];
#pragma unroll
        for (int j = 0; j < 8; j++)
            v[j] = __ldg(reinterpret_cast<const uint4*>(x + (size_t)s[j] * D) + lane);
#pragma unroll
        for (int j = 0; j < 8; j++) {
            const __half2* p = reinterpret_cast<const __half2*>(&v[j]);
#pragma unroll
            for (int q = 0; q < 4; q++) {
                float2 f = __half22float2(p[q]);
                acc[2 * q]     += f.x;
                acc[2 * q + 1] += f.y;
            }
        }
    }
    for (; i + 4 <= end; i += 4) {
        int s[4];
#pragma unroll
        for (int j = 0; j < 4; j++) s[j] = __ldg(ss + i + j);
        uint4 v[4];
#pragma unroll
        for (int j = 0; j < 4; j++)
            v[j] = __ldg(reinterpret_cast<const uint4*>(x + (size_t)s[j] * D) + lane);
#pragma unroll
        for (int j = 0; j < 4; j++) {
            const __half2* p = reinterpret_cast<const __half2*>(&v[j]);
#pragma unroll
            for (int q = 0; q < 4; q++) {
                float2 f = __half22float2(p[q]);
                acc[2 * q]     += f.x;
                acc[2 * q + 1] += f.y;
            }
        }
    }
    for (; i < end; i++) {
        const int s0 = __ldg(ss + i);
        uint4 v0 = __ldg(reinterpret_cast<const uint4*>(x + (size_t)s0 * D) + lane);
        const __half2* p = reinterpret_cast<const __half2*>(&v0);
#pragma unroll
        for (int q = 0; q < 4; q++) {
            float2 f = __half22float2(p[q]);
            acc[2 * q]     += f.x;
            acc[2 * q + 1] += f.y;
        }
    }

    const float inv = 1.0f / fmaxf((float)c, 1.0f);
    __half2 o[4];
#pragma unroll
    for (int q = 0; q < 4; q++)
        o[q] = __floats2half2_rn(acc[2 * q] * inv, acc[2 * q + 1] * inv);
    reinterpret_cast<uint4*>(mean + (size_t)w * D)[lane] = *reinterpret_cast<uint4*>(o);
}

// ---- fp16 mma helper (m16n8k16, fp32 accumulate) ----
__device__ __forceinline__ void mma_f16(float c[4], const uint32_t a[4], const uint32_t b[2]) {
    asm volatile(
        "mma.sync.aligned.m16n8k16.row.col.f32.f16.f16.f32 "
        "{%0,%1,%2,%3}, {%4,%5,%6,%7}, {%8,%9}, {%0,%1,%2,%3};"
        : "+f"(c[0]), "+f"(c[1]), "+f"(c[2]), "+f"(c[3])
        : "r"(a[0]), "r"(a[1]), "r"(a[2]), "r"(a[3]), "r"(b[0]), "r"(b[1]));
}

// ---- fused SAGE layer GEMM (fp16 tensor cores, fp32 accum), double-buffered smem:
//   out[m, j] = tanh( sum_k mean[m,k]*Wl[j,k] + sum_k xt[m,k]*Wr[j,k] + b[j] )
// A = [mean | xt] (M x 512, fp16), B^T = [Wl | Wr] (256 x 512, fp32 -> fp16).
__global__ __launch_bounds__(256) void k_sage_mma_h(
    const __half* __restrict__ meanh, const __half* __restrict__ xth,
    const float* __restrict__ Wl, const float* __restrict__ Wr,
    const float* __restrict__ bias,
    float* __restrict__ out, __half* __restrict__ out_h, int M)
{
    __shared__ uint32_t As[2][128][12];
    __shared__ uint32_t Bs[2][128][12];

    const int m0 = blockIdx.x * 128;
    const int n0 = blockIdx.y * 128;
    const int t  = threadIdx.x;

    const int lrow = t >> 1;
    const int half = t & 1;
    const int gm   = m0 + lrow;
    const bool mval = gm < M;
    const __half* mrow = meanh + (size_t)gm * D;
    const __half* xrow = xth  + (size_t)gm * D;
    const int gj = n0 + lrow;

    const int warp = t >> 5;
    const int lane = t & 31;
    const int gid  = lane >> 2;
    const int tig  = lane & 3;
    const int wm0  = (warp & 1) * 64;
    const int wn0  = (warp >> 1) * 32;

    float acc[4][4][4];
#pragma unroll
    for (int mf = 0; mf < 4; mf++)
#pragma unroll
        for (int nf = 0; nf < 4; nf++)
#pragma unroll
            for (int r = 0; r < 4; r++) acc[mf][nf][r] = 0.f;

    // slab loader: returns A uint4 and B (converted) uint4 for k-tile kt
    auto loadA = [&](int kt) -> uint4 {
        const int k0 = kt * 16;
        const bool in_agg = (k0 < 256);
        const int kk0 = in_agg ? k0 : (k0 - 256);
        uint4 av = make_uint4(0, 0, 0, 0);
        if (mval) {
            const __half* sp = (in_agg ? mrow : xrow) + kk0 + half * 8;
            av = *reinterpret_cast<const uint4*>(sp);
        }
        return av;
    };
    auto loadB = [&](int kt) -> uint4 {
        const int k0 = kt * 16;
        const bool in_agg = (k0 < 256);
        const int kk0 = in_agg ? k0 : (k0 - 256);
        const float* W  = in_agg ? Wl : Wr;
        const float* bp = W + (size_t)gj * D + kk0 + half * 8;
        float4 b0v = *reinterpret_cast<const float4*>(bp);
        float4 b1v = *reinterpret_cast<const float4*>(bp + 4);
        __half2 bh[4];
        bh[0] = __floats2half2_rn(b0v.x, b0v.y);
        bh[1] = __floats2half2_rn(b0v.z, b0v.w);
        bh[2] = __floats2half2_rn(b1v.x, b1v.y);
        bh[3] = __floats2half2_rn(b1v.z, b1v.w);
        return *reinterpret_cast<uint4*>(bh);
    };

    // prologue: fill stage 0
    {
        uint4 av = loadA(0);
        uint4 bv = loadB(0);
        *reinterpret_cast<uint4*>(&As[0][lrow][half * 4]) = av;
        *reinterpret_cast<uint4*>(&Bs[0][lrow][half * 4]) = bv;
    }
    __syncthreads();

    for (int kt = 0; kt < 32; kt++) {
        const int cur = kt & 1;
        const int nxt = cur ^ 1;

        // prefetch next slab into registers (overlaps with mma below)
        uint4 av, bv;
        if (kt < 31) {
            av = loadA(kt + 1);
            bv = loadB(kt + 1);
        }

        // mma on current stage
        uint32_t af[4][4], bf[4][2];
#pragma unroll
        for (int mf = 0; mf < 4; mf++) {
            const int r = wm0 + mf * 16 + gid;
            af[mf][0] = As[cur][r][tig];
            af[mf][1] = As[cur][r + 8][tig];
            af[mf][2] = As[cur][r][tig + 4];
            af[mf][3] = As[cur][r + 8][tig + 4];
        }
#pragma unroll
        for (int nf = 0; nf < 4; nf++) {
            const int c = wn0 + nf * 8 + gid;
            bf[nf][0] = Bs[cur][c][tig];
            bf[nf][1] = Bs[cur][c][tig + 4];
        }
#pragma unroll
        for (int mf = 0; mf < 4; mf++)
#pragma unroll
            for (int nf = 0; nf < 4; nf++)
                mma_f16(acc[mf][nf], af[mf], bf[nf]);

        // stage next slab
        if (kt < 31) {
            *reinterpret_cast<uint4*>(&As[nxt][lrow][half * 4]) = av;
            *reinterpret_cast<uint4*>(&Bs[nxt][lrow][half * 4]) = bv;
        }
        __syncthreads();
    }

#pragma unroll
    for (int nf = 0; nf < 4; nf++) {
        const int cb = n0 + wn0 + nf * 8 + tig * 2;
        const float bx = __ldg(bias + cb);
        const float by = __ldg(bias + cb + 1);
#pragma unroll
        for (int mf = 0; mf < 4; mf++) {
            const int r0 = m0 + wm0 + mf * 16 + gid;
            if (r0 < M) {
                float vx = tanhf(acc[mf][nf][0] + bx);
                float vy = tanhf(acc[mf][nf][1] + by);
                if (out)
                    *reinterpret_cast<float2*>(out + (size_t)r0 * D + cb) = make_float2(vx, vy);
                if (out_h)
                    *reinterpret_cast<__half2*>(out_h + (size_t)r0 * D + cb) =
                        __floats2half2_rn(vx, vy);
            }
            const int r1 = r0 + 8;
            if (r1 < M) {
                float vx = tanhf(acc[mf][nf][2] + bx);
                float vy = tanhf(acc[mf][nf][3] + by);
                if (out)
                    *reinterpret_cast<float2*>(out + (size_t)r1 * D + cb) = make_float2(vx, vy);
                if (out_h)
                    *reinterpret_cast<__half2*>(out_h + (size_t)r1 * D + cb) =
                        __floats2half2_rn(vx, vy);
            }
        }
    }
}

extern "C" void kernel_launch(void* const* d_in, const int* in_sizes, int n_in,
                              void* d_out, int out_size) {
    const float* nodes = (const float*)d_in[0];
    const float* W_l1  = (const float*)d_in[1];
    const float* b1    = (const float*)d_in[2];
    const float* W_r1  = (const float*)d_in[3];
    const float* W_l2  = (const float*)d_in[4];
    const float* b2    = (const float*)d_in[5];
    const float* W_r2  = (const float*)d_in[6];
    const int*   src1  = (const int*)d_in[7];
    const int*   dst1  = (const int*)d_in[8];
    const int*   src2  = (const int*)d_in[9];
    const int*   dst2  = (const int*)d_in[10];
    float* out = (float*)d_out;

    __half *nodesh, *h1h, *mean1h, *mean2h;
    int *cnt1, *start1, *cur1, *cnt2, *start2, *cur2, *ss1, *ss2;
    cudaGetSymbolAddress((void**)&nodesh, g_nodesh);
    cudaGetSymbolAddress((void**)&h1h,    g_h1h);
    cudaGetSymbolAddress((void**)&mean1h, g_mean1h);
    cudaGetSymbolAddress((void**)&mean2h, g_mean2h);
    cudaGetSymbolAddress((void**)&cnt1,   g_cnt1);
    cudaGetSymbolAddress((void**)&start1, g_start1);
    cudaGetSymbolAddress((void**)&cur1,   g_cur1);
    cudaGetSymbolAddress((void**)&cnt2,   g_cnt2);
    cudaGetSymbolAddress((void**)&start2, g_start2);
    cudaGetSymbolAddress((void**)&cur2,   g_cur2);
    cudaGetSymbolAddress((void**)&ss1,    g_ss1);
    cudaGetSymbolAddress((void**)&ss2,    g_ss2);

    // init counters
    k_init<<<(N1c + 255) / 256, 256>>>(cnt1, cnt2);
    // fp16 table + both histograms
    {
        int n8 = (int)(((size_t)N0c * D) / 8);
        k_cvt_hist<<<2368, 256>>>((const float4*)nodes, (uint4*)nodesh, n8,
                                  dst1, cnt1, E1c, dst2, cnt2, E2c);
    }

    // ---- layer 1 ----
    k_scan_t<<<1, 1024>>>((const int4*)cnt1, (int4*)start1, (int4*)cur1, N1c / 4);
    k_sidx<<<(E1c + 255) / 256, 256>>>(src1, dst1, cur1, ss1, E1c);
    k_gather_h<<<(N1c * 32 + 255) / 256, 256>>>(nodesh, ss1, start1, cnt1, mean1h, N1c);
    {
        dim3 grid((N1c + 127) / 128, 2);
        k_sage_mma_h<<<grid, 256>>>(mean1h, nodesh, W_l1, W_r1, b1,
                                    ((float*)0), h1h, N1c);
    }

    // ---- layer 2 ----
    k_scan_t<<<1, 1024>>>((const int4*)cnt2, (int4*)start2, (int4*)cur2, N2c / 4);
    k_sidx<<<(E2c + 255) / 256, 256>>>(src2, dst2, cur2, ss2, E2c);
    k_gather_h<<<(N2c * 32 + 255) / 256, 256>>>(h1h, ss2, start2, cnt2, mean2h, N2c);
    {
        dim3 grid((N2c + 127) / 128, 2);
        k_sage_mma_h<<<grid, 256>>>(mean2h, h1h, W_l2, W_r2, b2,
                                    out, ((__half*)0), N2c);
    }
}

// round 9
// speedup vs baseline: 1.7269x; 1.1836x over previous
#include <cuda_runtime.h>
#include <cuda_fp16.h>
#include <cstdint>

#define D    256
#define N0c  200000
#define N1c  40000
#define N2c  8000
#define E1c  1000000
#define E2c  200000

// ---- scratch (no allocations allowed) ----
__device__ __half g_nodesh[(size_t)N0c * D];   // fp16 node table (102 MB)
__device__ __half g_h1h[(size_t)N1c * D];      // fp16 h1
__device__ __half g_mean1h[(size_t)N1c * D];
__device__ __half g_mean2h[(size_t)N2c * D];
__device__ __half g_w1h[256 * 512];            // [Wl1 | Wr1] fp16
__device__ __half g_w2h[256 * 512];            // [Wl2 | Wr2]
__device__ int g_cnt1[N1c];
__device__ int g_start1[N1c];
__device__ int g_cur1[N1c];
__device__ int g_cnt2[N2c];
__device__ int g_start2[N2c];
__device__ int g_cur2[N2c];
__device__ int g_ss1[E1c];
__device__ int g_ss2[E2c];

// ---- streams/events for captured fork/join (created pre-main, no device mem) ----
static cudaStream_t s_cvt, s_sort2;
static cudaEvent_t ev_fork, ev_hist, ev_cvt_done, ev_sort2_done;
struct _StreamInit {
    _StreamInit() {
        cudaStreamCreateWithFlags(&s_cvt, cudaStreamNonBlocking);
        cudaStreamCreateWithFlags(&s_sort2, cudaStreamNonBlocking);
        cudaEventCreateWithFlags(&ev_fork, cudaEventDisableTiming);
        cudaEventCreateWithFlags(&ev_hist, cudaEventDisableTiming);
        cudaEventCreateWithFlags(&ev_cvt_done, cudaEventDisableTiming);
        cudaEventCreateWithFlags(&ev_sort2_done, cudaEventDisableTiming);
    }
};
static _StreamInit _si;

// ---------------------------------------------------------------------------
__global__ void k_init(int* __restrict__ c1, int* __restrict__ c2) {
    int i = blockIdx.x * blockDim.x + threadIdx.x;
    if (i < N1c) c1[i] = 0;
    if (i < N2c) c2[i] = 0;
}

// both dst histograms
__global__ void k_hist2(const int* __restrict__ dst1, int* __restrict__ cnt1, int e1,
                        const int* __restrict__ dst2, int* __restrict__ cnt2, int e2) {
    const int i0 = blockIdx.x * blockDim.x + threadIdx.x;
    const int stride = gridDim.x * blockDim.x;
    for (int i = i0; i < e1; i += stride) atomicAdd(&cnt1[__ldg(dst1 + i)], 1);
    for (int i = i0; i < e2; i += stride) atomicAdd(&cnt2[__ldg(dst2 + i)], 1);
}

// fp32 -> fp16 node table
__global__ void k_cvt(const float4* __restrict__ in, uint4* __restrict__ out, int n8) {
    int i = blockIdx.x * blockDim.x + threadIdx.x;
    int stride = gridDim.x * blockDim.x;
    for (; i < n8; i += stride) {
        float4 a = __ldg(in + 2 * i);
        float4 b = __ldg(in + 2 * i + 1);
        __half2 h[4];
        h[0] = __floats2half2_rn(a.x, a.y);
        h[1] = __floats2half2_rn(a.z, a.w);
        h[2] = __floats2half2_rn(b.x, b.y);
        h[3] = __floats2half2_rn(b.z, b.w);
        out[i] = *reinterpret_cast<uint4*>(h);
    }
}

// weights -> combined fp16 tables  w[n][k]: k<256 from Wl, k>=256 from Wr
__global__ void k_cvtw(const float* __restrict__ Wl1, const float* __restrict__ Wr1,
                       const float* __restrict__ Wl2, const float* __restrict__ Wr2,
                       uint4* __restrict__ w1h, uint4* __restrict__ w2h) {
    int i = blockIdx.x * blockDim.x + threadIdx.x;   // 0..32767
    if (i >= 32768) return;
    int layer = i >> 14;
    int li = i & 16383;
    int n = li >> 6;
    int seg = li & 63;
    const float* W = layer ? ((seg < 32) ? Wl2 : Wr2) : ((seg < 32) ? Wl1 : Wr1);
    int col = (seg & 31) * 8;
    const float4* p = reinterpret_cast<const float4*>(W + (size_t)n * 256 + col);
    float4 a = __ldg(p), b = __ldg(p + 1);
    __half2 h[4];
    h[0] = __floats2half2_rn(a.x, a.y);
    h[1] = __floats2half2_rn(a.z, a.w);
    h[2] = __floats2half2_rn(b.x, b.y);
    h[3] = __floats2half2_rn(b.z, b.w);
    (layer ? w2h : w1h)[li] = *reinterpret_cast<uint4*>(h);
}

__global__ __launch_bounds__(1024) void k_scan_t(
    const int4* __restrict__ cnt4, int4* __restrict__ start4,
    int4* __restrict__ cursor4, int n4)
{
    __shared__ int wsum[32];
    __shared__ int carry;
    const int tid = threadIdx.x;
    const int lane = tid & 31;
    const int wid = tid >> 5;
    if (tid == 0) carry = 0;
    __syncthreads();
    for (int base = 0; base < n4; base += 1024) {
        const int i = base + tid;
        int4 v = (i < n4) ? __ldg(cnt4 + i) : make_int4(0, 0, 0, 0);
        const int s = v.x + v.y + v.z + v.w;
        int x = s;
#pragma unroll
        for (int o = 1; o < 32; o <<= 1) {
            int y = __shfl_up_sync(~0u, x, o);
            if (lane >= o) x += y;
        }
        if (lane == 31) wsum[wid] = x;
        __syncthreads();
        if (tid < 32) {
            int w = wsum[tid];
#pragma unroll
            for (int o = 1; o < 32; o <<= 1) {
                int y = __shfl_up_sync(~0u, w, o);
                if (tid >= o) w += y;
            }
            wsum[tid] = w;
        }
        __syncthreads();
        const int wpref = (wid > 0) ? wsum[wid - 1] : 0;
        const int e = x - s + wpref + carry;
        if (i < n4) {
            int4 st;
            st.x = e; st.y = e + v.x; st.z = st.y + v.y; st.w = st.z + v.z;
            start4[i] = st;
            cursor4[i] = st;
        }
        __syncthreads();
        if (tid == 0) carry += wsum[31];
        __syncthreads();
    }
}

__global__ void k_sidx(const int* __restrict__ src, const int* __restrict__ dst,
                       int* __restrict__ cursor, int* __restrict__ ss, int ne) {
    int i = blockIdx.x * blockDim.x + threadIdx.x;
    if (i < ne) {
        int d = __ldg(dst + i);
        int p = atomicAdd(&cursor[d], 1);
        ss[p] = __ldg(src + i);
    }
}

__global__ __launch_bounds__(256) void k_gather_h(
    const __half* __restrict__ x, const int* __restrict__ ss,
    const int* __restrict__ start, const int* __restrict__ cnt,
    __half* __restrict__ mean, int n)
{
    int w = (blockIdx.x * blockDim.x + threadIdx.x) >> 5;
    if (w >= n) return;
    const int lane = threadIdx.x & 31;
    const int beg = __ldg(start + w);
    const int c = __ldg(cnt + w);
    const int end = beg + c;

    float acc[8];
#pragma unroll
    for (int j = 0; j < 8; j++) acc[j] = 0.f;

    int i = beg;
    for (; i + 8 <= end; i += 8) {
        int s[8];
#pragma unroll
        for (int j = 0; j < 8; j++) s[j] = __ldg(ss + i + j);
        uint4 v[8];
#pragma unroll
        for (int j = 0; j < 8; j++)
            v[j] = __ldg(reinterpret_cast<const uint4*>(x + (size_t)s[j] * D) + lane);
#pragma unroll
        for (int j = 0; j < 8; j++) {
            const __half2* p = reinterpret_cast<const __half2*>(&v[j]);
#pragma unroll
            for (int q = 0; q < 4; q++) {
                float2 f = __half22float2(p[q]);
                acc[2 * q]     += f.x;
                acc[2 * q + 1] += f.y;
            }
        }
    }
    for (; i + 4 <= end; i += 4) {
        int s[4];
#pragma unroll
        for (int j = 0; j < 4; j++) s[j] = __ldg(ss + i + j);
        uint4 v[4];
#pragma unroll
        for (int j = 0; j < 4; j++)
            v[j] = __ldg(reinterpret_cast<const uint4*>(x + (size_t)s[j] * D) + lane);
#pragma unroll
        for (int j = 0; j < 4; j++) {
            const __half2* p = reinterpret_cast<const __half2*>(&v[j]);
#pragma unroll
            for (int q = 0; q < 4; q++) {
                float2 f = __half22float2(p[q]);
                acc[2 * q]     += f.x;
                acc[2 * q + 1] += f.y;
            }
        }
    }
    for (; i < end; i++) {
        const int s0 = __ldg(ss + i);
        uint4 v0 = __ldg(reinterpret_cast<const uint4*>(x + (size_t)s0 * D) + lane);
        const __half2* p = reinterpret_cast<const __half2*>(&v0);
#pragma unroll
        for (int q = 0; q < 4; q++) {
            float2 f = __half22float2(p[q]);
            acc[2 * q]     += f.x;
            acc[2 * q + 1] += f.y;
        }
    }

    const float inv = 1.0f / fmaxf((float)c, 1.0f);
    __half2 o[4];
#pragma unroll
    for (int q = 0; q < 4; q++)
        o[q] = __floats2half2_rn(acc[2 * q] * inv, acc[2 * q + 1] * inv);
    reinterpret_cast<uint4*>(mean + (size_t)w * D)[lane] = *reinterpret_cast<uint4*>(o);
}

// ---- fp16 mma helper (m16n8k16, fp32 accumulate) ----
__device__ __forceinline__ void mma_f16(float c[4], const uint32_t a[4], const uint32_t b[2]) {
    asm volatile(
        "mma.sync.aligned.m16n8k16.row.col.f32.f16.f16.f32 "
        "{%0,%1,%2,%3}, {%4,%5,%6,%7}, {%8,%9}, {%0,%1,%2,%3};"
        : "+f"(c[0]), "+f"(c[1]), "+f"(c[2]), "+f"(c[3])
        : "r"(a[0]), "r"(a[1]), "r"(a[2]), "r"(a[3]), "r"(b[0]), "r"(b[1]));
}

// ---- fused SAGE layer GEMM (fp16 mma.sync, fp32 accum), double-buffered smem.
// A = [mean | xt] (M x 512 fp16), B^T = wcomb (256 x 512 fp16), out = tanh(A B^T + bias)
__global__ __launch_bounds__(256) void k_sage_mma_h(
    const __half* __restrict__ meanh, const __half* __restrict__ xth,
    const __half* __restrict__ wcomb, const float* __restrict__ bias,
    float* __restrict__ out, __half* __restrict__ out_h, int M)
{
    __shared__ uint32_t As[2][128][12];
    __shared__ uint32_t Bs[2][128][12];

    const int m0 = blockIdx.x * 128;
    const int n0 = blockIdx.y * 128;
    const int t  = threadIdx.x;

    const int lrow = t >> 1;
    const int half = t & 1;
    const int gm   = m0 + lrow;
    const bool mval = gm < M;
    const __half* mrow = meanh + (size_t)gm * D;
    const __half* xrow = xth  + (size_t)gm * D;
    const __half* wrow = wcomb + (size_t)(n0 + lrow) * 512;

    const int warp = t >> 5;
    const int lane = t & 31;
    const int gid  = lane >> 2;
    const int tig  = lane & 3;
    const int wm0  = (warp & 1) * 64;
    const int wn0  = (warp >> 1) * 32;

    float acc[4][4][4];
#pragma unroll
    for (int mf = 0; mf < 4; mf++)
#pragma unroll
        for (int nf = 0; nf < 4; nf++)
#pragma unroll
            for (int r = 0; r < 4; r++) acc[mf][nf][r] = 0.f;

    auto loadA = [&](int kt) -> uint4 {
        const int k0 = kt * 16;
        const bool in_agg = (k0 < 256);
        const int kk0 = in_agg ? k0 : (k0 - 256);
        uint4 av = make_uint4(0, 0, 0, 0);
        if (mval) {
            const __half* sp = (in_agg ? mrow : xrow) + kk0 + half * 8;
            av = *reinterpret_cast<const uint4*>(sp);
        }
        return av;
    };
    auto loadB = [&](int kt) -> uint4 {
        return *reinterpret_cast<const uint4*>(wrow + kt * 16 + half * 8);
    };

    {
        uint4 av = loadA(0);
        uint4 bv = loadB(0);
        *reinterpret_cast<uint4*>(&As[0][lrow][half * 4]) = av;
        *reinterpret_cast<uint4*>(&Bs[0][lrow][half * 4]) = bv;
    }
    __syncthreads();

    for (int kt = 0; kt < 32; kt++) {
        const int cur = kt & 1;
        const int nxt = cur ^ 1;

        uint4 av, bv;
        if (kt < 31) {
            av = loadA(kt + 1);
            bv = loadB(kt + 1);
        }

        uint32_t af[4][4], bf[4][2];
#pragma unroll
        for (int mf = 0; mf < 4; mf++) {
            const int r = wm0 + mf * 16 + gid;
            af[mf][0] = As[cur][r][tig];
            af[mf][1] = As[cur][r + 8][tig];
            af[mf][2] = As[cur][r][tig + 4];
            af[mf][3] = As[cur][r + 8][tig + 4];
        }
#pragma unroll
        for (int nf = 0; nf < 4; nf++) {
            const int c = wn0 + nf * 8 + gid;
            bf[nf][0] = Bs[cur][c][tig];
            bf[nf][1] = Bs[cur][c][tig + 4];
        }
#pragma unroll
        for (int mf = 0; mf < 4; mf++)
#pragma unroll
            for (int nf = 0; nf < 4; nf++)
                mma_f16(acc[mf][nf], af[mf], bf[nf]);

        if (kt < 31) {
            *reinterpret_cast<uint4*>(&As[nxt][lrow][half * 4]) = av;
            *reinterpret_cast<uint4*>(&Bs[nxt][lrow][half * 4]) = bv;
        }
        __syncthreads();
    }

#pragma unroll
    for (int nf = 0; nf < 4; nf++) {
        const int cb = n0 + wn0 + nf * 8 + tig * 2;
        const float bx = __ldg(bias + cb);
        const float by = __ldg(bias + cb + 1);
#pragma unroll
        for (int mf = 0; mf < 4; mf++) {
            const int r0 = m0 + wm0 + mf * 16 + gid;
            if (r0 < M) {
                float vx = tanhf(acc[mf][nf][0] + bx);
                float vy = tanhf(acc[mf][nf][1] + by);
                if (out)
                    *reinterpret_cast<float2*>(out + (size_t)r0 * D + cb) = make_float2(vx, vy);
                if (out_h)
                    *reinterpret_cast<__half2*>(out_h + (size_t)r0 * D + cb) =
                        __floats2half2_rn(vx, vy);
            }
            const int r1 = r0 + 8;
            if (r1 < M) {
                float vx = tanhf(acc[mf][nf][2] + bx);
                float vy = tanhf(acc[mf][nf][3] + by);
                if (out)
                    *reinterpret_cast<float2*>(out + (size_t)r1 * D + cb) = make_float2(vx, vy);
                if (out_h)
                    *reinterpret_cast<__half2*>(out_h + (size_t)r1 * D + cb) =
                        __floats2half2_rn(vx, vy);
            }
        }
    }
}

// ---------------------------------------------------------------------------
extern "C" void kernel_launch(void* const* d_in, const int* in_sizes, int n_in,
                              void* d_out, int out_size) {
    const float* nodes = (const float*)d_in[0];
    const float* W_l1  = (const float*)d_in[1];
    const float* b1    = (const float*)d_in[2];
    const float* W_r1  = (const float*)d_in[3];
    const float* W_l2  = (const float*)d_in[4];
    const float* b2    = (const float*)d_in[5];
    const float* W_r2  = (const float*)d_in[6];
    const int*   src1  = (const int*)d_in[7];
    const int*   dst1  = (const int*)d_in[8];
    const int*   src2  = (const int*)d_in[9];
    const int*   dst2  = (const int*)d_in[10];
    float* out = (float*)d_out;

    __half *nodesh, *h1h, *mean1h, *mean2h, *w1h, *w2h;
    int *cnt1, *start1, *cur1, *cnt2, *start2, *cur2, *ss1, *ss2;
    cudaGetSymbolAddress((void**)&nodesh, g_nodesh);
    cudaGetSymbolAddress((void**)&h1h,    g_h1h);
    cudaGetSymbolAddress((void**)&mean1h, g_mean1h);
    cudaGetSymbolAddress((void**)&mean2h, g_mean2h);
    cudaGetSymbolAddress((void**)&w1h,    g_w1h);
    cudaGetSymbolAddress((void**)&w2h,    g_w2h);
    cudaGetSymbolAddress((void**)&cnt1,   g_cnt1);
    cudaGetSymbolAddress((void**)&start1, g_start1);
    cudaGetSymbolAddress((void**)&cur1,   g_cur1);
    cudaGetSymbolAddress((void**)&cnt2,   g_cnt2);
    cudaGetSymbolAddress((void**)&start2, g_start2);
    cudaGetSymbolAddress((void**)&cur2,   g_cur2);
    cudaGetSymbolAddress((void**)&ss1,    g_ss1);
    cudaGetSymbolAddress((void**)&ss2,    g_ss2);

    // ---- default stream: init counters ----
    k_init<<<(N1c + 255) / 256, 256>>>(cnt1, cnt2);
    cudaEventRecord(ev_fork, 0);

    // ---- stream B (forked): fp16 table + weight conversion ----
    cudaStreamWaitEvent(s_cvt, ev_fork, 0);
    {
        int n8 = (int)(((size_t)N0c * D) / 8);
        k_cvt<<<2368, 256, 0, s_cvt>>>((const float4*)nodes, (uint4*)nodesh, n8);
    }
    k_cvtw<<<128, 256, 0, s_cvt>>>(W_l1, W_r1, W_l2, W_r2, (uint4*)w1h, (uint4*)w2h);
    cudaEventRecord(ev_cvt_done, s_cvt);

    // ---- default stream: histograms then layer-1 sort ----
    k_hist2<<<1184, 256>>>(dst1, cnt1, E1c, dst2, cnt2, E2c);
    cudaEventRecord(ev_hist, 0);

    // ---- stream C (forked after hist): layer-2 sort ----
    cudaStreamWaitEvent(s_sort2, ev_hist, 0);
    k_scan_t<<<1, 1024, 0, s_sort2>>>((const int4*)cnt2, (int4*)start2, (int4*)cur2, N2c / 4);
    k_sidx<<<(E2c + 255) / 256, 256, 0, s_sort2>>>(src2, dst2, cur2, ss2, E2c);
    cudaEventRecord(ev_sort2_done, s_sort2);

    // ---- default stream: layer-1 sort ----
    k_scan_t<<<1, 1024>>>((const int4*)cnt1, (int4*)start1, (int4*)cur1, N1c / 4);
    k_sidx<<<(E1c + 255) / 256, 256>>>(src1, dst1, cur1, ss1, E1c);

    // join conversions, then layer-1 compute
    cudaStreamWaitEvent(0, ev_cvt_done, 0);
    k_gather_h<<<(N1c * 32 + 255) / 256, 256>>>(nodesh, ss1, start1, cnt1, mean1h, N1c);
    {
        dim3 grid((N1c + 127) / 128, 2);
        k_sage_mma_h<<<grid, 256>>>(mean1h, nodesh, w1h, b1, ((float*)0), h1h, N1c);
    }

    // join layer-2 sort, then layer-2 compute
    cudaStreamWaitEvent(0, ev_sort2_done, 0);
    k_gather_h<<<(N2c * 32 + 255) / 256, 256>>>(h1h, ss2, start2, cnt2, mean2h, N2c);
    {
        dim3 grid((N2c + 127) / 128, 2);
        k_sage_mma_h<<<grid, 256>>>(mean2h, h1h, w2h, b2, out, ((__half*)0), N2c);
    }
}